// round 16
// baseline (speedup 1.0000x reference)
#include <cuda_runtime.h>
#include <cuda_bf16.h>
#include <cuda_fp16.h>
#include <math.h>
#include <stdint.h>

#define BATCH 4096
#define DIM   1024
#define EPS_W 0.05f
#define REG_W 0.1f
#define NITER 10
#define INV_B (1.0f/4096.0f)

// fp8 K scaling: K' = CBIG * K ; vh = V / CVS
#define CBIG 16777216.0f          // 2^24
#define LNC  16.635532f           // ln(2^24)
#define CVS  8192.0f              // 2^13
#define CUCV 2048.0f              // CBIG / CVS

// GEMM tiling (bf16 mma.sync — proven best; tcgen05 is 'a'-gated in this build)
#define BM 128
#define BN 128
#define BK 32
#define APAD 8
#define ASTRIDE (BK + APAD)
#define STAGES 4
#define GEMM_SMEM (STAGES * (BM + BN) * ASTRIDE * 2)   // 81920 bytes

// persistent Sinkhorn: 128 blocks x 1024 threads, one block per SM,
// 32-row K' stripe resident in SHARED MEMORY (immune to L1 flushes).
#define NB 128
#define NT 1024
#define RPB 32
#define CPB 32
#define STRIPE_B (RPB * BATCH)                        // 131072 B fp8
#define SINK_SMEM (STRIPE_B + BATCH * 2 + BATCH * 4)  // stripe + vh + v = 155648

// ---------------- scratch (static device globals; no allocation) ----------------
__device__ __nv_bfloat16 g_an[(size_t)BATCH * DIM];   // 8 MB
__device__ __nv_bfloat16 g_tn[(size_t)BATCH * DIM];   // 8 MB
__device__ __nv_bfloat16 g_Kh[(size_t)BATCH * BATCH]; // 32 MB: M (bf16) from GEMM
__device__ float g_part[(size_t)NB * BATCH];          // 2 MB partials [block][col]
__device__ float g_v[BATCH];                          // true V (fp32)
__device__ __half g_vh[BATCH];                        // V / CVS (fp16)
__device__ float g_col[BATCH];
__device__ float g_ce[BATCH];
__device__ float g_rowsum[BATCH];
__device__ unsigned int g_maxbits;
__device__ unsigned int g_barcnt;
__device__ unsigned int g_barsense;

// ---------------- helpers ----------------
__device__ __forceinline__ uint32_t smem_u32(const void* p) {
    uint32_t a;
    asm("{ .reg .u64 t; cvta.to.shared.u64 t, %1; cvt.u32.u64 %0, t; }" : "=r"(a) : "l"(p));
    return a;
}
__device__ __forceinline__ void cp_async16(uint32_t dst, const void* src) {
    asm volatile("cp.async.cg.shared.global [%0], [%1], 16;" :: "r"(dst), "l"(src));
}
#define CP_COMMIT() asm volatile("cp.async.commit_group;" ::: "memory")
#define CP_WAIT(n)  asm volatile("cp.async.wait_group %0;" :: "n"(n) : "memory")

__device__ __forceinline__ void ldmatrix_x4(uint32_t& r0, uint32_t& r1, uint32_t& r2,
                                            uint32_t& r3, uint32_t addr) {
    asm volatile("ldmatrix.sync.aligned.m8n8.x4.shared.b16 {%0,%1,%2,%3}, [%4];"
                 : "=r"(r0), "=r"(r1), "=r"(r2), "=r"(r3) : "r"(addr));
}
__device__ __forceinline__ void mma_bf16(float& c0, float& c1, float& c2, float& c3,
                                         uint32_t a0, uint32_t a1, uint32_t a2, uint32_t a3,
                                         uint32_t b0, uint32_t b1) {
    asm volatile("mma.sync.aligned.m16n8k16.row.col.f32.bf16.bf16.f32 "
                 "{%0,%1,%2,%3}, {%4,%5,%6,%7}, {%8,%9}, {%0,%1,%2,%3};"
                 : "+f"(c0), "+f"(c1), "+f"(c2), "+f"(c3)
                 : "r"(a0), "r"(a1), "r"(a2), "r"(a3), "r"(b0), "r"(b1));
}
__device__ __forceinline__ unsigned ld_acquire(unsigned* p) {
    unsigned v;
    asm volatile("ld.acquire.gpu.global.u32 %0, [%1];" : "=r"(v) : "l"(p) : "memory");
    return v;
}
__device__ __forceinline__ void st_release(unsigned* p, unsigned v) {
    asm volatile("st.release.gpu.global.u32 [%0], %1;" :: "l"(p), "r"(v) : "memory");
}
__device__ __forceinline__ unsigned short pack_e4m3(float hi, float lo) {
    unsigned short r;
    asm("cvt.rn.satfinite.e4m3x2.f32 %0, %1, %2;" : "=h"(r) : "f"(hi), "f"(lo));
    return r;
}
__device__ __forceinline__ __half2 unpack_e4m3(unsigned short h) {
    unsigned r;
    asm("cvt.rn.f16x2.e4m3x2 %0, %1;" : "=r"(r) : "h"(h));
    return *reinterpret_cast<__half2*>(&r);
}

__device__ __forceinline__ float blockReduceSum1024(float v, float* sh) {
    __syncthreads();
    int lane = threadIdx.x & 31;
    int w    = threadIdx.x >> 5;
    #pragma unroll
    for (int o = 16; o > 0; o >>= 1) v += __shfl_down_sync(0xffffffffu, v, o);
    if (lane == 0) sh[w] = v;
    __syncthreads();
    v = (threadIdx.x < 32) ? sh[threadIdx.x] : 0.0f;
    if (w == 0) {
        #pragma unroll
        for (int o = 16; o > 0; o >>= 1) v += __shfl_down_sync(0xffffffffu, v, o);
    }
    if (threadIdx.x == 0) sh[0] = v;
    __syncthreads();
    return sh[0];
}

// ---------------- kernels ----------------

__global__ void init_kernel() {
    if (threadIdx.x == 0) {
        g_maxbits = 0u;
        g_barcnt = 0u;
        g_barsense = 0u;
    }
}

__global__ void normalize_kernel(const float* __restrict__ audio,
                                 const float* __restrict__ text) {
    __shared__ float sh[8];
    int row = blockIdx.x;
    const float* src;
    __nv_bfloat16* dst;
    if (row < BATCH) { src = audio + (size_t)row * DIM;           dst = g_an + (size_t)row * DIM; }
    else             { src = text  + (size_t)(row - BATCH) * DIM; dst = g_tn + (size_t)(row - BATCH) * DIM; }
    float4 v = ((const float4*)src)[threadIdx.x];
    float ss = v.x*v.x + v.y*v.y + v.z*v.z + v.w*v.w;
    int lane = threadIdx.x & 31, w = threadIdx.x >> 5;
    #pragma unroll
    for (int o = 16; o > 0; o >>= 1) ss += __shfl_down_sync(0xffffffffu, ss, o);
    if (lane == 0) sh[w] = ss;
    __syncthreads();
    float tot = 0.0f;
    if (threadIdx.x < 8) tot = sh[threadIdx.x];
    if (w == 0) {
        #pragma unroll
        for (int o = 4; o > 0; o >>= 1) tot += __shfl_down_sync(0xffffffffu, tot, o);
        if (lane == 0) sh[0] = tot;
    }
    __syncthreads();
    float inv = rsqrtf(sh[0]);
    __nv_bfloat162 h0 = __floats2bfloat162_rn(v.x * inv, v.y * inv);
    __nv_bfloat162 h1 = __floats2bfloat162_rn(v.z * inv, v.w * inv);
    ((__nv_bfloat162*)dst)[2 * threadIdx.x + 0] = h0;
    ((__nv_bfloat162*)dst)[2 * threadIdx.x + 1] = h1;
}

// bf16 mma.sync GEMM: M = 1 - an @ tn^T -> g_Kh (bf16), track global max.
__global__ void __launch_bounds__(256, 2) gemm_mma_kernel() {
    extern __shared__ char gsm[];
    typedef __nv_bfloat16 TileA[BM][ASTRIDE];
    typedef __nv_bfloat16 TileB[BN][ASTRIDE];
    TileA* As = (TileA*)gsm;
    TileB* Bs = (TileB*)(gsm + STAGES * BM * ASTRIDE * 2);
    __shared__ float sred[256];

    int t    = threadIdx.x;
    int wid  = t >> 5;
    int lane = t & 31;
    int warp_m = wid & 1;
    int warp_n = wid >> 1;
    int row0 = blockIdx.y * BM;
    int col0 = blockIdx.x * BN;

    int cid0 = t, cid1 = t + 256;
    int ar0 = cid0 >> 2, ak0 = (cid0 & 3) * 8;
    int ar1 = cid1 >> 2, ak1 = (cid1 & 3) * 8;

    float acc[4][4][4];
    #pragma unroll
    for (int i = 0; i < 4; i++)
        #pragma unroll
        for (int j = 0; j < 4; j++)
            #pragma unroll
            for (int r = 0; r < 4; r++) acc[i][j][r] = 0.0f;

    auto load_stage = [&](int s, int k0) {
        cp_async16(smem_u32(&As[s][ar0][ak0]), &g_an[(size_t)(row0 + ar0) * DIM + k0 + ak0]);
        cp_async16(smem_u32(&As[s][ar1][ak1]), &g_an[(size_t)(row0 + ar1) * DIM + k0 + ak1]);
        cp_async16(smem_u32(&Bs[s][ar0][ak0]), &g_tn[(size_t)(col0 + ar0) * DIM + k0 + ak0]);
        cp_async16(smem_u32(&Bs[s][ar1][ak1]), &g_tn[(size_t)(col0 + ar1) * DIM + k0 + ak1]);
        CP_COMMIT();
    };

    load_stage(0, 0);
    load_stage(1, BK);
    load_stage(2, 2 * BK);

    const int NK = DIM / BK;
    for (int c = 0; c < NK; c++) {
        int buf = c & 3;
        CP_WAIT(2);
        __syncthreads();
        if (c + 3 < NK) load_stage((c + 3) & 3, (c + 3) * BK);
        else            CP_COMMIT();

        #pragma unroll
        for (int kk = 0; kk < BK; kk += 16) {
            uint32_t a[4][4], b[4][2];
            #pragma unroll
            for (int i = 0; i < 4; i++) {
                uint32_t addr = smem_u32(&As[buf][warp_m * 64 + i * 16 + (lane & 15)]
                                            [kk + (lane >> 4) * 8]);
                ldmatrix_x4(a[i][0], a[i][1], a[i][2], a[i][3], addr);
            }
            #pragma unroll
            for (int j = 0; j < 4; j += 2) {
                uint32_t addr = smem_u32(&Bs[buf][warp_n * 32 + j * 8 + (lane >> 4) * 8 + (lane & 7)]
                                            [kk + ((lane >> 3) & 1) * 8]);
                ldmatrix_x4(b[j][0], b[j][1], b[j+1][0], b[j+1][1], addr);
            }
            #pragma unroll
            for (int i = 0; i < 4; i++)
                #pragma unroll
                for (int j = 0; j < 4; j++)
                    mma_bf16(acc[i][j][0], acc[i][j][1], acc[i][j][2], acc[i][j][3],
                             a[i][0], a[i][1], a[i][2], a[i][3], b[j][0], b[j][1]);
        }
    }

    float bmax = 0.0f;
    int rr = lane >> 2;
    int cc = (lane & 3) * 2;
    #pragma unroll
    for (int i = 0; i < 4; i++) {
        #pragma unroll
        for (int j = 0; j < 4; j++) {
            float m0 = 1.0f - acc[i][j][0];
            float m1 = 1.0f - acc[i][j][1];
            float m2 = 1.0f - acc[i][j][2];
            float m3 = 1.0f - acc[i][j][3];
            bmax = fmaxf(bmax, fmaxf(fmaxf(m0, m1), fmaxf(m2, m3)));
            int row = row0 + warp_m * 64 + i * 16 + rr;
            int col = col0 + warp_n * 32 + j * 8 + cc;
            *(__nv_bfloat162*)&g_Kh[(size_t)row * BATCH + col]       = __floats2bfloat162_rn(m0, m1);
            *(__nv_bfloat162*)&g_Kh[(size_t)(row + 8) * BATCH + col] = __floats2bfloat162_rn(m2, m3);
        }
    }
    sred[t] = bmax;
    __syncthreads();
    for (int s = 128; s > 0; s >>= 1) {
        if (t < s) sred[t] = fmaxf(sred[t], sred[t + s]);
        __syncthreads();
    }
    if (t == 0) atomicMax(&g_maxbits, __float_as_uint(sred[0]));
}

// ---------------- persistent Sinkhorn: K' stripe in SMEM ----------------
// Invariants: U = B*u (O(1)); V = true v; g_vh = V/CVS; K' = CBIG*K (e4m3 in smem).

__device__ unsigned int d_dummy;

struct SinkStatic {
    float u[RPB];
    __half2 uh[RPB];
    unsigned int sense;
    float sh[32];
};

// proven barrier (R8): threadfence + flat atomics
__device__ __forceinline__ void grid_bar(SinkStatic* S) {
    __syncthreads();
    if (threadIdx.x == 0) {
        unsigned int target = S->sense ^ 1u;
        S->sense = target;
        __threadfence();
        unsigned int old = atomicAdd(&g_barcnt, 1u);
        if (old == NB - 1u) {
            g_barcnt = 0u;
            st_release(&g_barsense, target);
        } else {
            while (ld_acquire(&g_barsense) != target) { }
        }
    }
    __syncthreads();
}

// K' = exp(M*sc + lnC) -> e4m3 smem stripe (one time)
__device__ __forceinline__ void phaseFirst(unsigned char* stripe, int r0, float sc) {
    int t = threadIdx.x;
    #pragma unroll
    for (int i = 0; i < 16; i++) {
        int idx = t + 1024 * i;      // 0..16383
        int r = idx >> 9;            // 0..31
        int c = idx & 511;           // uint4 chunk of 8 bf16
        uint4 m = ((const uint4*)(g_Kh + (size_t)(r0 + r) * BATCH))[c];
        const __nv_bfloat162* h = reinterpret_cast<const __nv_bfloat162*>(&m);
        float f[8];
        #pragma unroll
        for (int j = 0; j < 4; j++) {
            float2 p = __bfloat1622float2(h[j]);
            f[2*j]   = __expf(fmaf(p.x, sc, LNC));
            f[2*j+1] = __expf(fmaf(p.y, sc, LNC));
        }
        unsigned short u0 = pack_e4m3(f[1], f[0]);
        unsigned short u1 = pack_e4m3(f[3], f[2]);
        unsigned short u2 = pack_e4m3(f[5], f[4]);
        unsigned short u3 = pack_e4m3(f[7], f[6]);
        uint2 w;
        w.x = (unsigned)u0 | ((unsigned)u1 << 16);
        w.y = (unsigned)u2 | ((unsigned)u3 << 16);
        *(uint2*)(stripe + r * BATCH + c * 8) = w;
    }
    __syncthreads();
}

// col partials: P_j = sum_r U_r * K'_rj  (thread per 4 cols; K' from smem)
template<bool FIRST>
__device__ __forceinline__ void phaseA(SinkStatic* S, unsigned char* stripe, int b) {
    int t = threadIdx.x;
    __half2 one = __floats2half2_rn(1.0f, 1.0f);
    __half2 z = __floats2half2_rn(0.0f, 0.0f);
    __half2 a0 = z, a1 = z;
    #pragma unroll 8
    for (int r = 0; r < RPB; r++) {
        unsigned q = *(const unsigned*)(stripe + r * BATCH + 4 * t);
        __half2 U2 = FIRST ? one : S->uh[r];
        __half2 k0 = unpack_e4m3((unsigned short)(q & 0xFFFFu));
        __half2 k1 = unpack_e4m3((unsigned short)(q >> 16));
        a0 = __hfma2(k0, U2, a0);
        a1 = __hfma2(k1, U2, a1);
    }
    float2 f0 = __half22float2(a0);
    float2 f1 = __half22float2(a1);
    ((float4*)(g_part + (size_t)b * BATCH))[t] = make_float4(f0.x, f0.y, f1.x, f1.y);
}

// row dots: U = CUCV / dot(K', vh_smem)  (warp per row)
__device__ __forceinline__ void phaseC(SinkStatic* S, unsigned char* stripe, const __half* svh) {
    int warp = threadIdx.x >> 5, lane = threadIdx.x & 31;
    const uint4* hv4 = (const uint4*)svh;
    __half2 z = __floats2half2_rn(0.0f, 0.0f);
    __half2 acc[8] = {z, z, z, z, z, z, z, z};
    #pragma unroll
    for (int i = 0; i < 8; i++) {
        int slot = lane + 32 * i;    // 16 cols per slot
        uint4 k = *(const uint4*)(stripe + warp * BATCH + slot * 16);
        uint4 va = hv4[2*slot], vb = hv4[2*slot + 1];
        __half2 hv[8];
        *(uint4*)&hv[0] = va;
        *(uint4*)&hv[4] = vb;
        unsigned kw[4] = {k.x, k.y, k.z, k.w};
        #pragma unroll
        for (int w2 = 0; w2 < 4; w2++) {
            __half2 k0 = unpack_e4m3((unsigned short)(kw[w2] & 0xFFFFu));
            __half2 k1 = unpack_e4m3((unsigned short)(kw[w2] >> 16));
            acc[2*w2]     = __hfma2(k0, hv[2*w2],     acc[2*w2]);
            acc[2*w2 + 1] = __hfma2(k1, hv[2*w2 + 1], acc[2*w2 + 1]);
        }
    }
    float s = 0.0f;
    #pragma unroll
    for (int j = 0; j < 8; j++) {
        float2 f = __half22float2(acc[j]);
        s += f.x + f.y;
    }
    #pragma unroll
    for (int o = 16; o > 0; o >>= 1) s += __shfl_down_sync(0xffffffffu, s, o);
    if (lane == 0) {
        float U = CUCV / s;
        S->u[warp]  = U;
        S->uh[warp] = __floats2half2_rn(U, U);
    }
    __syncthreads();
}

// reduce partials (warp per col, 32 cols/block). MODE 0: V=CBIG/s2 ; MODE 1: col=s2*(INV_B/CBIG)*V
template<int MODE>
__device__ __forceinline__ void phaseB(int b) {
    int warp = threadIdx.x >> 5, lane = threadIdx.x & 31;
    int c = b * CPB + warp;
    float s = 0.0f;
    #pragma unroll
    for (int k = 0; k < 4; k++)
        s += g_part[(size_t)(lane + 32 * k) * BATCH + c];
    #pragma unroll
    for (int o = 16; o > 0; o >>= 1) s += __shfl_down_sync(0xffffffffu, s, o);
    if (lane == 0) {
        if (MODE == 0) {
            float V = CBIG / s;
            g_v[c]  = V;
            g_vh[c] = __float2half(V * (1.0f / CVS));
        } else {
            g_col[c] = s * (INV_B / CBIG) * g_v[c];
        }
    }
    __syncthreads();
}

__device__ __forceinline__ void load_vh(__half* svh) {
    int t = threadIdx.x;
    if (t < 512) ((uint4*)svh)[t] = ((const uint4*)g_vh)[t];   // 8 KB
    __syncthreads();
}
__device__ __forceinline__ void load_v(float* sv) {
    int t = threadIdx.x;
    ((float4*)sv)[t] = ((const float4*)g_v)[t];                // 16 KB (1024 x 16B)
    __syncthreads();
}

// row stats (fp32): pi = (U*INV_B/CBIG) * K' * V  (warp per row)
__device__ __forceinline__ void phaseR(SinkStatic* S, unsigned char* stripe, const float* sv, int r0) {
    int warp = threadIdx.x >> 5, lane = threadIdx.x & 31;
    int r = r0 + warp;
    float c = S->u[warp] * (INV_B / CBIG);
    float se = 0.0f, rs = 0.0f;
    #pragma unroll
    for (int i = 0; i < 8; i++) {
        int slot = lane + 32 * i;
        uint4 k = *(const uint4*)(stripe + warp * BATCH + slot * 16);
        const float4* vv = (const float4*)(sv + 16 * slot);
        unsigned kw[4] = {k.x, k.y, k.z, k.w};
        #pragma unroll
        for (int w2 = 0; w2 < 4; w2++) {
            float2 fa = __half22float2(unpack_e4m3((unsigned short)(kw[w2] & 0xFFFFu)));
            float2 fb = __half22float2(unpack_e4m3((unsigned short)(kw[w2] >> 16)));
            float4 V4 = vv[w2];
            float p0 = c * fa.x * V4.x;
            float p1 = c * fa.y * V4.y;
            float p2 = c * fb.x * V4.z;
            float p3 = c * fb.y * V4.w;
            se += __expf(p0) + __expf(p1) + __expf(p2) + __expf(p3);
            rs += p0 + p1 + p2 + p3;
        }
    }
    #pragma unroll
    for (int o = 16; o > 0; o >>= 1) {
        se += __shfl_down_sync(0xffffffffu, se, o);
        rs += __shfl_down_sync(0xffffffffu, rs, o);
    }
    if (lane == 0) {
        unsigned char db = stripe[warp * BATCH + r];
        float2 kd2 = __half22float2(unpack_e4m3((unsigned short)db));
        float diag = c * kd2.x * sv[r];
        g_ce[r] = logf(se) - diag;
        g_rowsum[r] = rs;
    }
}

__global__ void __launch_bounds__(NT, 1) sink_persist_kernel(float* __restrict__ out) {
    extern __shared__ char dsm[];
    unsigned char* stripe = (unsigned char*)dsm;                 // 131072 B
    __half* svh = (__half*)(dsm + STRIPE_B);                     // 8192 B
    float*  sv  = (float*)(dsm + STRIPE_B + BATCH * 2);          // 16384 B
    __shared__ SinkStatic S;

    int b = blockIdx.x;
    int t = threadIdx.x;
    int r0 = b * RPB;

    if (t == 0) S.sense = 0u;
    __syncthreads();

    float mx = __uint_as_float(g_maxbits);
    float sc = -1.0f / (EPS_W * mx);

    // one-time: convert M -> K' into smem stripe; partials with U = 1
    phaseFirst(stripe, r0, sc);
    phaseA<true>(&S, stripe, b);
    grid_bar(&S);
    phaseB<0>(b);
    grid_bar(&S);

    for (int it = 1; it < NITER; it++) {
        load_vh(svh);
        phaseC(&S, stripe, svh);
        phaseA<false>(&S, stripe, b);
        grid_bar(&S);
        phaseB<0>(b);
        grid_bar(&S);
    }

    load_vh(svh);
    phaseC(&S, stripe, svh);
    phaseA<false>(&S, stripe, b);
    grid_bar(&S);
    phaseB<1>(b);
    load_v(sv);
    phaseR(&S, stripe, sv, r0);
    grid_bar(&S);

    if (b == 0) {
        float ce = 0.0f, klr = 0.0f, klc = 0.0f;
        for (int i = t; i < BATCH; i += NT) {
            ce += g_ce[i];
            float rs = g_rowsum[i];
            klr += rs * (logf(rs) - INV_B);
            float cs = g_col[i];
            klc += cs * (logf(cs) - INV_B);
        }
        float ce_t  = blockReduceSum1024(ce,  S.sh);
        float klr_t = blockReduceSum1024(klr, S.sh);
        float klc_t = blockReduceSum1024(klc, S.sh);
        if (t == 0)
            out[0] = ce_t * INV_B + REG_W * (klc_t * INV_B + klr_t * INV_B);
    }
}

// ---------------- launcher ----------------
extern "C" void kernel_launch(void* const* d_in, const int* in_sizes, int n_in,
                              void* d_out, int out_size) {
    const float* audio = (const float*)d_in[0];
    const float* text  = (const float*)d_in[1];
    float* out = (float*)d_out;

    cudaFuncSetAttribute(gemm_mma_kernel,
                         cudaFuncAttributeMaxDynamicSharedMemorySize, GEMM_SMEM);
    cudaFuncSetAttribute(sink_persist_kernel,
                         cudaFuncAttributeMaxDynamicSharedMemorySize, SINK_SMEM);

    init_kernel<<<1, 32>>>();
    normalize_kernel<<<2 * BATCH, 256>>>(audio, text);
    gemm_mma_kernel<<<dim3(BATCH / BN, BATCH / BM), 256, GEMM_SMEM>>>();
    sink_persist_kernel<<<NB, NT, SINK_SMEM>>>(out);
}

// round 17
// speedup vs baseline: 1.0708x; 1.0708x over previous
#include <cuda_runtime.h>
#include <cuda_bf16.h>
#include <math.h>
#include <stdint.h>

#define BATCH 4096
#define DIM   1024
#define EPS_W 0.05f
#define REG_W 0.1f
#define NITER 10
#define INV_B (1.0f/4096.0f)

// GEMM tiling (bf16 mma.sync; tcgen05 is 'a'-gated in this build)
#define BM 128
#define BN 128
#define BK 32
#define APAD 8
#define ASTRIDE (BK + APAD)
#define STAGES 4
#define GEMM_SMEM (STAGES * (BM + BN) * ASTRIDE * 2)   // 81920 bytes

// persistent Sinkhorn (R11 structure — best measured)
#define NB 256
#define NT 512
#define RPB 16
#define CPB 16

// ---------------- scratch (static device globals; no allocation) ----------------
__device__ __nv_bfloat16 g_an[(size_t)BATCH * DIM];   // 8 MB
__device__ __nv_bfloat16 g_tn[(size_t)BATCH * DIM];   // 8 MB
__device__ __nv_bfloat16 g_Kh[(size_t)BATCH * BATCH]; // 32 MB: M then K in place (bf16)
__device__ float g_part[(size_t)NB * BATCH];          // 4 MB partials [block][col]
__device__ float g_v[BATCH];
__device__ __nv_bfloat16 g_vh[BATCH];                 // bf16 copy of v for HFMA2 dots
__device__ float g_col[BATCH];
__device__ float g_ce[BATCH];
__device__ float g_rowsum[BATCH];
__device__ unsigned int g_maxbits;
__device__ unsigned int g_barcnt;
__device__ unsigned int g_barsense;

// ---------------- helpers ----------------
__device__ __forceinline__ uint32_t smem_u32(const void* p) {
    uint32_t a;
    asm("{ .reg .u64 t; cvta.to.shared.u64 t, %1; cvt.u32.u64 %0, t; }" : "=r"(a) : "l"(p));
    return a;
}
__device__ __forceinline__ void cp_async16(uint32_t dst, const void* src) {
    asm volatile("cp.async.cg.shared.global [%0], [%1], 16;" :: "r"(dst), "l"(src));
}
#define CP_COMMIT() asm volatile("cp.async.commit_group;" ::: "memory")
#define CP_WAIT(n)  asm volatile("cp.async.wait_group %0;" :: "n"(n) : "memory")

__device__ __forceinline__ void ldmatrix_x4(uint32_t& r0, uint32_t& r1, uint32_t& r2,
                                            uint32_t& r3, uint32_t addr) {
    asm volatile("ldmatrix.sync.aligned.m8n8.x4.shared.b16 {%0,%1,%2,%3}, [%4];"
                 : "=r"(r0), "=r"(r1), "=r"(r2), "=r"(r3) : "r"(addr));
}
__device__ __forceinline__ void mma_bf16(float& c0, float& c1, float& c2, float& c3,
                                         uint32_t a0, uint32_t a1, uint32_t a2, uint32_t a3,
                                         uint32_t b0, uint32_t b1) {
    asm volatile("mma.sync.aligned.m16n8k16.row.col.f32.bf16.bf16.f32 "
                 "{%0,%1,%2,%3}, {%4,%5,%6,%7}, {%8,%9}, {%0,%1,%2,%3};"
                 : "+f"(c0), "+f"(c1), "+f"(c2), "+f"(c3)
                 : "r"(a0), "r"(a1), "r"(a2), "r"(a3), "r"(b0), "r"(b1));
}
__device__ __forceinline__ unsigned ld_acquire(unsigned* p) {
    unsigned v;
    asm volatile("ld.acquire.gpu.global.u32 %0, [%1];" : "=r"(v) : "l"(p) : "memory");
    return v;
}
__device__ __forceinline__ void st_release(unsigned* p, unsigned v) {
    asm volatile("st.release.gpu.global.u32 [%0], %1;" :: "l"(p), "r"(v) : "memory");
}

__device__ __forceinline__ float blockReduceSum512(float v, float* sh) {
    __syncthreads();
    int lane = threadIdx.x & 31;
    int w    = threadIdx.x >> 5;
    #pragma unroll
    for (int o = 16; o > 0; o >>= 1) v += __shfl_down_sync(0xffffffffu, v, o);
    if (lane == 0) sh[w] = v;
    __syncthreads();
    v = (threadIdx.x < 16) ? sh[threadIdx.x] : 0.0f;
    if (w == 0) {
        #pragma unroll
        for (int o = 8; o > 0; o >>= 1) v += __shfl_down_sync(0xffffffffu, v, o);
    }
    if (threadIdx.x == 0) sh[0] = v;
    __syncthreads();
    return sh[0];
}

// ---------------- kernels ----------------

__global__ void init_kernel() {
    if (threadIdx.x == 0) {
        g_maxbits = 0u;
        g_barcnt = 0u;
        g_barsense = 0u;
    }
}

__global__ void normalize_kernel(const float* __restrict__ audio,
                                 const float* __restrict__ text) {
    __shared__ float sh[8];
    int row = blockIdx.x;
    const float* src;
    __nv_bfloat16* dst;
    if (row < BATCH) { src = audio + (size_t)row * DIM;           dst = g_an + (size_t)row * DIM; }
    else             { src = text  + (size_t)(row - BATCH) * DIM; dst = g_tn + (size_t)(row - BATCH) * DIM; }
    float4 v = ((const float4*)src)[threadIdx.x];
    float ss = v.x*v.x + v.y*v.y + v.z*v.z + v.w*v.w;
    int lane = threadIdx.x & 31, w = threadIdx.x >> 5;
    #pragma unroll
    for (int o = 16; o > 0; o >>= 1) ss += __shfl_down_sync(0xffffffffu, ss, o);
    if (lane == 0) sh[w] = ss;
    __syncthreads();
    float tot = 0.0f;
    if (threadIdx.x < 8) tot = sh[threadIdx.x];
    if (w == 0) {
        #pragma unroll
        for (int o = 4; o > 0; o >>= 1) tot += __shfl_down_sync(0xffffffffu, tot, o);
        if (lane == 0) sh[0] = tot;
    }
    __syncthreads();
    float inv = rsqrtf(sh[0]);
    __nv_bfloat162 h0 = __floats2bfloat162_rn(v.x * inv, v.y * inv);
    __nv_bfloat162 h1 = __floats2bfloat162_rn(v.z * inv, v.w * inv);
    ((__nv_bfloat162*)dst)[2 * threadIdx.x + 0] = h0;
    ((__nv_bfloat162*)dst)[2 * threadIdx.x + 1] = h1;
}

// bf16 mma.sync GEMM: M = 1 - an @ tn^T -> g_Kh (bf16), track global max.
// 4-stage cp.async; B-fragments for the whole chunk hoisted before the k-step loop.
__global__ void __launch_bounds__(256, 2) gemm_mma_kernel() {
    extern __shared__ char gsm[];
    typedef __nv_bfloat16 TileA[BM][ASTRIDE];
    typedef __nv_bfloat16 TileB[BN][ASTRIDE];
    TileA* As = (TileA*)gsm;
    TileB* Bs = (TileB*)(gsm + STAGES * BM * ASTRIDE * 2);

    int t    = threadIdx.x;
    int lane = t & 31;
    int wid  = t >> 5;
    int warp_m = wid & 1;
    int warp_n = wid >> 1;
    int row0 = blockIdx.y * BM;
    int col0 = blockIdx.x * BN;

    int cid0 = t, cid1 = t + 256;
    int ar0 = cid0 >> 2, ak0 = (cid0 & 3) * 8;
    int ar1 = cid1 >> 2, ak1 = (cid1 & 3) * 8;

    float acc[4][4][4];
    #pragma unroll
    for (int i = 0; i < 4; i++)
        #pragma unroll
        for (int j = 0; j < 4; j++)
            #pragma unroll
            for (int r = 0; r < 4; r++) acc[i][j][r] = 0.0f;

    auto load_stage = [&](int s, int k0) {
        cp_async16(smem_u32(&As[s][ar0][ak0]), &g_an[(size_t)(row0 + ar0) * DIM + k0 + ak0]);
        cp_async16(smem_u32(&As[s][ar1][ak1]), &g_an[(size_t)(row0 + ar1) * DIM + k0 + ak1]);
        cp_async16(smem_u32(&Bs[s][ar0][ak0]), &g_tn[(size_t)(col0 + ar0) * DIM + k0 + ak0]);
        cp_async16(smem_u32(&Bs[s][ar1][ak1]), &g_tn[(size_t)(col0 + ar1) * DIM + k0 + ak1]);
        CP_COMMIT();
    };

    load_stage(0, 0);
    load_stage(1, BK);
    load_stage(2, 2 * BK);

    const int NK = DIM / BK;
    for (int c = 0; c < NK; c++) {
        int buf = c & 3;
        CP_WAIT(2);
        __syncthreads();
        if (c + 3 < NK) load_stage((c + 3) & 3, (c + 3) * BK);
        else            CP_COMMIT();

        // hoist ALL B fragments for this chunk (both k-steps)
        uint32_t b[2][4][2];
        #pragma unroll
        for (int ks = 0; ks < 2; ks++) {
            #pragma unroll
            for (int j = 0; j < 4; j += 2) {
                uint32_t addr = smem_u32(&Bs[buf][warp_n * 32 + j * 8 + (lane >> 4) * 8 + (lane & 7)]
                                            [ks * 16 + ((lane >> 3) & 1) * 8]);
                ldmatrix_x4(b[ks][j][0], b[ks][j][1], b[ks][j+1][0], b[ks][j+1][1], addr);
            }
        }
        #pragma unroll
        for (int ks = 0; ks < 2; ks++) {
            uint32_t a[4][4];
            #pragma unroll
            for (int i = 0; i < 4; i++) {
                uint32_t addr = smem_u32(&As[buf][warp_m * 64 + i * 16 + (lane & 15)]
                                            [ks * 16 + (lane >> 4) * 8]);
                ldmatrix_x4(a[i][0], a[i][1], a[i][2], a[i][3], addr);
            }
            #pragma unroll
            for (int i = 0; i < 4; i++)
                #pragma unroll
                for (int j = 0; j < 4; j++)
                    mma_bf16(acc[i][j][0], acc[i][j][1], acc[i][j][2], acc[i][j][3],
                             a[i][0], a[i][1], a[i][2], a[i][3], b[ks][j][0], b[ks][j][1]);
        }
    }

    // epilogue: M = 1 - C, store, warp-level max + atomicMax (no smem tree)
    float bmax = 0.0f;
    int rr = lane >> 2;
    int cc = (lane & 3) * 2;
    #pragma unroll
    for (int i = 0; i < 4; i++) {
        #pragma unroll
        for (int j = 0; j < 4; j++) {
            float m0 = 1.0f - acc[i][j][0];
            float m1 = 1.0f - acc[i][j][1];
            float m2 = 1.0f - acc[i][j][2];
            float m3 = 1.0f - acc[i][j][3];
            bmax = fmaxf(bmax, fmaxf(fmaxf(m0, m1), fmaxf(m2, m3)));
            int row = row0 + warp_m * 64 + i * 16 + rr;
            int col = col0 + warp_n * 32 + j * 8 + cc;
            *(__nv_bfloat162*)&g_Kh[(size_t)row * BATCH + col]       = __floats2bfloat162_rn(m0, m1);
            *(__nv_bfloat162*)&g_Kh[(size_t)(row + 8) * BATCH + col] = __floats2bfloat162_rn(m2, m3);
        }
    }
    #pragma unroll
    for (int o = 16; o > 0; o >>= 1)
        bmax = fmaxf(bmax, __shfl_xor_sync(0xffffffffu, bmax, o));
    if (lane == 0) atomicMax(&g_maxbits, __float_as_uint(bmax));   // all M >= 0
}

// ---------------- persistent Sinkhorn (R11: bf16 K, HFMA2) ----------------

struct SinkShared {
    float v[BATCH];              // 16 KB fp32 v (final stats only)
    float u[RPB];
    __nv_bfloat162 uh[RPB];      // splatted bf16x2 u
    unsigned int sense;
    float red[32][CPB];
    float sh[16];
};

// flat sense-reversing grid barrier (proven)
__device__ __forceinline__ void grid_bar(SinkShared* S) {
    __syncthreads();
    if (threadIdx.x == 0) {
        unsigned int target = S->sense ^ 1u;
        S->sense = target;
        __threadfence();
        unsigned int old = atomicAdd(&g_barcnt, 1u);
        if (old == NB - 1u) {
            g_barcnt = 0u;
            st_release(&g_barsense, target);
        } else {
            while (ld_acquire(&g_barsense) != target) { }
        }
    }
    __syncthreads();
}

// iteration 0: K = exp(M*sc) in place; col partials with u = INV_B  (fp32 path)
__device__ __forceinline__ void phaseFirst(SinkShared* S, int b, int r0, float sc) {
    int t = threadIdx.x;
    float acc[8];
    #pragma unroll
    for (int j = 0; j < 8; j++) acc[j] = 0.0f;

    #pragma unroll
    for (int rb = 0; rb < RPB; rb += 4) {
        uint4 q[4];
        #pragma unroll
        for (int rr = 0; rr < 4; rr++)
            q[rr] = ((uint4*)(g_Kh + (size_t)(r0 + rb + rr) * BATCH))[t];
        #pragma unroll
        for (int rr = 0; rr < 4; rr++) {
            __nv_bfloat162* h = reinterpret_cast<__nv_bfloat162*>(&q[rr]);
            float f[8];
            #pragma unroll
            for (int j = 0; j < 4; j++) {
                float2 p = __bfloat1622float2(h[j]);
                f[2*j] = __expf(p.x * sc); f[2*j+1] = __expf(p.y * sc);
            }
            #pragma unroll
            for (int j = 0; j < 4; j++)
                h[j] = __floats2bfloat162_rn(f[2*j], f[2*j+1]);
            ((uint4*)(g_Kh + (size_t)(r0 + rb + rr) * BATCH))[t] = q[rr];
            #pragma unroll
            for (int j = 0; j < 8; j++) acc[j] += f[j];
        }
    }
    float4* pp = (float4*)(g_part + (size_t)b * BATCH);
    pp[2*t + 0] = make_float4(acc[0]*INV_B, acc[1]*INV_B, acc[2]*INV_B, acc[3]*INV_B);
    pp[2*t + 1] = make_float4(acc[4]*INV_B, acc[5]*INV_B, acc[6]*INV_B, acc[7]*INV_B);
}

// row dots via packed bf16 HFMA2: u_r = INV_B / dot(K[r,:], vh) ; warp per row
__device__ __forceinline__ void phaseC(SinkShared* S, int r0) {
    int warp = threadIdx.x >> 5, lane = threadIdx.x & 31;
    const uint4* row = (const uint4*)(g_Kh + (size_t)(r0 + warp) * BATCH);
    const uint4* vh = (const uint4*)g_vh;
    __nv_bfloat162 z = __float2bfloat162_rn(0.0f);
    __nv_bfloat162 a0 = z, a1 = z, a2 = z, a3 = z;
    #pragma unroll
    for (int i = 0; i < 16; i++) {
        int slot = lane + 32 * i;
        uint4 k = row[slot];
        uint4 vv = vh[slot];
        const __nv_bfloat162* hk = reinterpret_cast<const __nv_bfloat162*>(&k);
        const __nv_bfloat162* hv = reinterpret_cast<const __nv_bfloat162*>(&vv);
        a0 = __hfma2(hk[0], hv[0], a0);
        a1 = __hfma2(hk[1], hv[1], a1);
        a2 = __hfma2(hk[2], hv[2], a2);
        a3 = __hfma2(hk[3], hv[3], a3);
    }
    float2 f0 = __bfloat1622float2(a0);
    float2 f1 = __bfloat1622float2(a1);
    float2 f2 = __bfloat1622float2(a2);
    float2 f3 = __bfloat1622float2(a3);
    float s = (f0.x + f0.y) + (f1.x + f1.y) + (f2.x + f2.y) + (f3.x + f3.y);
    #pragma unroll
    for (int o = 16; o > 0; o >>= 1) s += __shfl_down_sync(0xffffffffu, s, o);
    if (lane == 0) {
        float u = INV_B / s;
        S->u[warp] = u;
        S->uh[warp] = __float2bfloat162_rn(u);
    }
    __syncthreads();
}

// col partials via packed bf16 HFMA2: part[b][j] = sum_r u_r K[r][j]
__device__ __forceinline__ void phaseA(SinkShared* S, int b, int r0) {
    int t = threadIdx.x;
    __nv_bfloat162 z = __float2bfloat162_rn(0.0f);
    __nv_bfloat162 a0 = z, a1 = z, a2 = z, a3 = z;
    #pragma unroll
    for (int rb = 0; rb < RPB; rb += 4) {
        uint4 q[4];
        #pragma unroll
        for (int rr = 0; rr < 4; rr++)
            q[rr] = ((const uint4*)(g_Kh + (size_t)(r0 + rb + rr) * BATCH))[t];
        #pragma unroll
        for (int rr = 0; rr < 4; rr++) {
            __nv_bfloat162 ur = S->uh[rb + rr];
            const __nv_bfloat162* h = reinterpret_cast<const __nv_bfloat162*>(&q[rr]);
            a0 = __hfma2(h[0], ur, a0);
            a1 = __hfma2(h[1], ur, a1);
            a2 = __hfma2(h[2], ur, a2);
            a3 = __hfma2(h[3], ur, a3);
        }
    }
    float2 f0 = __bfloat1622float2(a0);
    float2 f1 = __bfloat1622float2(a1);
    float2 f2 = __bfloat1622float2(a2);
    float2 f3 = __bfloat1622float2(a3);
    float4* pp = (float4*)(g_part + (size_t)b * BATCH);
    pp[2*t + 0] = make_float4(f0.x, f0.y, f1.x, f1.y);
    pp[2*t + 1] = make_float4(f2.x, f2.y, f3.x, f3.y);
}

// reduce partials for this block's 16 cols. MODE 0: v = INV_B/s ; MODE 1: col = s * v
template<int MODE>
__device__ __forceinline__ void phaseB(SinkShared* S, int b) {
    int t = threadIdx.x;
    int c0 = b * CPB;
    int p  = t >> 4;
    int cl = t & 15;
    float s = 0.0f;
    #pragma unroll
    for (int i = 0; i < 8; i++)
        s += g_part[(size_t)(p + 32 * i) * BATCH + c0 + cl];
    S->red[p][cl] = s;
    __syncthreads();
    if (t < CPB) {
        float s2 = 0.0f;
        #pragma unroll
        for (int g = 0; g < 32; g++) s2 += S->red[g][t];
        if (MODE == 0) {
            float v = INV_B / s2;
            g_v[c0 + t]  = v;
            g_vh[c0 + t] = __float2bfloat16(v);
        } else {
            g_col[c0 + t] = s2 * g_v[c0 + t];
        }
    }
    __syncthreads();
}

__device__ __forceinline__ void load_v(SinkShared* S) {
    int t = threadIdx.x;
    float4* d = (float4*)S->v;
    const float4* s = (const float4*)g_v;
    d[t]       = s[t];
    d[t + 512] = s[t + 512];
    __syncthreads();
}

// row stats (fp32): se = sum exp(pi), rs = sum pi, ce = log(se) - pi_rr
__device__ __forceinline__ void phaseR(SinkShared* S, int r0) {
    int warp = threadIdx.x >> 5, lane = threadIdx.x & 31;
    int r = r0 + warp;
    float ur = S->u[warp];
    const uint4* row = (const uint4*)(g_Kh + (size_t)r * BATCH);
    float se = 0.0f, rs = 0.0f;
    #pragma unroll
    for (int i = 0; i < 16; i += 4) {
        uint4 q[4];
        #pragma unroll
        for (int j2 = 0; j2 < 4; j2++) q[j2] = row[lane + 32 * (i + j2)];
        #pragma unroll
        for (int j2 = 0; j2 < 4; j2++) {
            int slot = lane + 32 * (i + j2);
            const float4* vv = (const float4*)(S->v + 8 * slot);
            float4 va = vv[0], vb = vv[1];
            __nv_bfloat162* h = reinterpret_cast<__nv_bfloat162*>(&q[j2]);
            float2 f0 = __bfloat1622float2(h[0]);
            float2 f1 = __bfloat1622float2(h[1]);
            float2 f2 = __bfloat1622float2(h[2]);
            float2 f3 = __bfloat1622float2(h[3]);
            float p0 = ur * f0.x * va.x, p1 = ur * f0.y * va.y;
            float p2 = ur * f1.x * va.z, p3 = ur * f1.y * va.w;
            float p4 = ur * f2.x * vb.x, p5 = ur * f2.y * vb.y;
            float p6 = ur * f3.x * vb.z, p7 = ur * f3.y * vb.w;
            se += __expf(p0) + __expf(p1) + __expf(p2) + __expf(p3)
                + __expf(p4) + __expf(p5) + __expf(p6) + __expf(p7);
            rs += p0 + p1 + p2 + p3 + p4 + p5 + p6 + p7;
        }
    }
    #pragma unroll
    for (int o = 16; o > 0; o >>= 1) {
        se += __shfl_down_sync(0xffffffffu, se, o);
        rs += __shfl_down_sync(0xffffffffu, rs, o);
    }
    if (lane == 0) {
        float kd = __bfloat162float(g_Kh[(size_t)r * BATCH + r]);
        float diag = ur * kd * S->v[r];
        g_ce[r] = logf(se) - diag;
        g_rowsum[r] = rs;
    }
}

__global__ void __launch_bounds__(NT, 2) sink_persist_kernel(float* __restrict__ out) {
    __shared__ SinkShared S;
    int b = blockIdx.x;
    int t = threadIdx.x;
    int r0 = b * RPB;

    if (t == 0) S.sense = 0u;
    __syncthreads();

    float mx = __uint_as_float(g_maxbits);
    float sc = -1.0f / (EPS_W * mx);

    phaseFirst(&S, b, r0, sc);
    grid_bar(&S);
    phaseB<0>(&S, b);
    grid_bar(&S);

    for (int it = 1; it < NITER; it++) {
        phaseC(&S, r0);
        phaseA(&S, b, r0);
        grid_bar(&S);
        phaseB<0>(&S, b);
        grid_bar(&S);
    }

    phaseC(&S, r0);                // u_10 from v_10
    phaseA(&S, b, r0);             // partials with u_10
    grid_bar(&S);
    phaseB<1>(&S, b);              // g_col = colsum(pi)
    load_v(&S);
    phaseR(&S, r0);                // row stats
    grid_bar(&S);

    if (b == 0) {
        float ce = 0.0f, klr = 0.0f, klc = 0.0f;
        for (int i = t; i < BATCH; i += NT) {
            ce += g_ce[i];
            float rs = g_rowsum[i];
            klr += rs * (logf(rs) - INV_B);
            float cs = g_col[i];
            klc += cs * (logf(cs) - INV_B);
        }
        float ce_t  = blockReduceSum512(ce,  S.sh);
        float klr_t = blockReduceSum512(klr, S.sh);
        float klc_t = blockReduceSum512(klc, S.sh);
        if (t == 0)
            out[0] = ce_t * INV_B + REG_W * (klc_t * INV_B + klr_t * INV_B);
    }
}

// ---------------- launcher ----------------
extern "C" void kernel_launch(void* const* d_in, const int* in_sizes, int n_in,
                              void* d_out, int out_size) {
    const float* audio = (const float*)d_in[0];
    const float* text  = (const float*)d_in[1];
    float* out = (float*)d_out;

    cudaFuncSetAttribute(gemm_mma_kernel,
                         cudaFuncAttributeMaxDynamicSharedMemorySize, GEMM_SMEM);

    init_kernel<<<1, 32>>>();
    normalize_kernel<<<2 * BATCH, 256>>>(audio, text);
    gemm_mma_kernel<<<dim3(BATCH / BN, BATCH / BM), 256, GEMM_SMEM>>>();
    sink_persist_kernel<<<NB, NT>>>(out);
}